// round 4
// baseline (speedup 1.0000x reference)
#include <cuda_runtime.h>

#define Bz   16
#define Tz   512
#define Dz   384
#define Kz   3
#define ROWS (Bz*Tz)       // 8192
#define TM   32            // rows per block
#define NKS  (Kz*48)       // 144 k-steps of 8
#define NT   48            // n-tiles of 8 (384/8)
#define PSTR 388           // padded patch stride in floats (388 % 32 == 4 -> conflict-free frags)

// ---------------- scratch (device globals) ----------------
__device__ float4 g_wf1[NKS*NT*32];   // weights in mma-fragment layout (hi0,hi1,lo0,lo1)
__device__ float4 g_wf2[NKS*NT*32];
__device__ float  g_h1[ROWS*Dz];
__device__ float  g_h2[ROWS*Dz];
__device__ int    g_cum[ROWS];

__device__ __forceinline__ float tf32_trunc(float x) {
    return __uint_as_float(__float_as_uint(x) & 0xFFFFE000u);
}

__device__ __forceinline__ void mma_tf32(float* d,
    unsigned a0, unsigned a1, unsigned a2, unsigned a3,
    unsigned b0, unsigned b1)
{
    asm volatile(
        "mma.sync.aligned.m16n8k8.row.col.f32.tf32.tf32.f32 "
        "{%0,%1,%2,%3},{%4,%5,%6,%7},{%8,%9},{%0,%1,%2,%3};"
        : "+f"(d[0]), "+f"(d[1]), "+f"(d[2]), "+f"(d[3])
        : "r"(a0), "r"(a1), "r"(a2), "r"(a3), "r"(b0), "r"(b1));
}

// ---------------- weight prep: w[O][I][K] -> fragment-major hi/lo ----------------
__global__ void prep_w_kernel(const float* __restrict__ w, int stage) {
    float4* wf = stage ? g_wf2 : g_wf1;
    int idx = blockIdx.x * blockDim.x + threadIdx.x;
    if (idx >= NKS*NT*32) return;
    int lane = idx & 31;
    int nt   = (idx >> 5) % NT;
    int ks   = idx / (NT*32);
    int tig = lane & 3, gid = lane >> 2;
    int tap = ks / 48, kc = ks % 48;
    int ic0 = kc*8 + tig;
    int och = nt*8 + gid;
    float b0 = w[(size_t)och*Dz*Kz + (size_t)ic0*Kz + tap];
    float b1 = w[(size_t)och*Dz*Kz + (size_t)(ic0+4)*Kz + tap];
    float h0 = tf32_trunc(b0), h1 = tf32_trunc(b1);
    wf[idx] = make_float4(h0, h1, b0 - h0, b1 - h1);
}

// ---------------- fused conv1d(K=3) + LN + ReLU via tensor-core 3xTF32 ----------------
// 8 warps; all cover the same 32 rows, each owns 48 output cols (6 n-tiles).
__global__ void __launch_bounds__(256, 2) conv_ln_relu_mma(
    const float* __restrict__ x_in,
    const float* __restrict__ bias,
    const float* __restrict__ gamma,
    const float* __restrict__ beta,
    int stage)
{
    extern __shared__ float sm[];          // patch (TM+2)xPSTR floats; reused as C stash
    __shared__ float s_mean[TM], s_rstd[TM];

    const float*  in  = stage ? g_h1  : x_in;
    const float4* wf  = stage ? g_wf2 : g_wf1;
    float*        out = stage ? g_h2  : g_h1;

    const int tid  = threadIdx.x;
    const int warp = tid >> 5, lane = tid & 31;
    const int tig  = lane & 3, gid = lane >> 2;

    const int tilesPerB = Tz / TM;                 // 16
    const int b  = blockIdx.x / tilesPerB;
    const int t0 = (blockIdx.x % tilesPerB) * TM;
    const float* inB = in + (size_t)b * Tz * Dz;

    // ---- fill patch rows t0-1 .. t0+TM (34 rows), zero-padded at batch edges ----
    for (int i = tid; i < (TM+2)*(Dz/4); i += 256) {
        int pr = i / (Dz/4), c4 = i % (Dz/4);
        int t = t0 + pr - 1;
        float4 v = make_float4(0.f, 0.f, 0.f, 0.f);
        if (t >= 0 && t < Tz) v = *(const float4*)(inB + (size_t)t*Dz + c4*4);
        *(float4*)(sm + pr*PSTR + c4*4) = v;
    }
    __syncthreads();

    // ---- GEMM: warp covers 32 rows x 48 cols ----
    float acc[2][6][4];
    #pragma unroll
    for (int mt = 0; mt < 2; mt++)
        #pragma unroll
        for (int nl = 0; nl < 6; nl++)
            #pragma unroll
            for (int e = 0; e < 4; e++) acc[mt][nl][e] = 0.f;

    #pragma unroll 1
    for (int tap = 0; tap < Kz; tap++) {
        #pragma unroll 1
        for (int kc = 0; kc < 48; kc++) {
            const int ks = tap*48 + kc;
            const int c0 = kc*8 + tig;

            // A fragments from patch (conflict-free due to PSTR % 32 == 4)
            unsigned ahi[2][4], alo[2][4];
            #pragma unroll
            for (int mt = 0; mt < 2; mt++) {
                const float* pr = sm + (mt*16 + gid + tap) * PSTR;
                float a0 = pr[c0];
                float a1 = pr[8*PSTR + c0];
                float a2 = pr[c0 + 4];
                float a3 = pr[8*PSTR + c0 + 4];
                unsigned h0 = __float_as_uint(a0) & 0xFFFFE000u;
                unsigned h1 = __float_as_uint(a1) & 0xFFFFE000u;
                unsigned h2 = __float_as_uint(a2) & 0xFFFFE000u;
                unsigned h3 = __float_as_uint(a3) & 0xFFFFE000u;
                ahi[mt][0] = h0; alo[mt][0] = __float_as_uint(a0 - __uint_as_float(h0));
                ahi[mt][1] = h1; alo[mt][1] = __float_as_uint(a1 - __uint_as_float(h1));
                ahi[mt][2] = h2; alo[mt][2] = __float_as_uint(a2 - __uint_as_float(h2));
                ahi[mt][3] = h3; alo[mt][3] = __float_as_uint(a3 - __uint_as_float(h3));
            }

            const float4* wfk = wf + ((size_t)ks*NT + warp*6)*32 + lane;
            #pragma unroll
            for (int nl = 0; nl < 6; nl++) {
                float4 wv = wfk[nl*32];
                unsigned bh0 = __float_as_uint(wv.x), bh1 = __float_as_uint(wv.y);
                unsigned bl0 = __float_as_uint(wv.z), bl1 = __float_as_uint(wv.w);
                #pragma unroll
                for (int mt = 0; mt < 2; mt++) {
                    mma_tf32(acc[mt][nl], ahi[mt][0], ahi[mt][1], ahi[mt][2], ahi[mt][3], bh0, bh1);
                    mma_tf32(acc[mt][nl], ahi[mt][0], ahi[mt][1], ahi[mt][2], ahi[mt][3], bl0, bl1);
                    mma_tf32(acc[mt][nl], alo[mt][0], alo[mt][1], alo[mt][2], alo[mt][3], bh0, bh1);
                }
            }
        }
    }

    // ---- stash C (+bias) into smem (reuse patch region) ----
    __syncthreads();
    #pragma unroll
    for (int mt = 0; mt < 2; mt++) {
        int r0 = mt*16 + gid;
        #pragma unroll
        for (int nl = 0; nl < 6; nl++) {
            int c = warp*48 + nl*8 + tig*2;
            float bv0 = __ldg(bias + c), bv1 = __ldg(bias + c + 1);
            sm[r0*PSTR + c]       = acc[mt][nl][0] + bv0;
            sm[r0*PSTR + c + 1]   = acc[mt][nl][1] + bv1;
            sm[(r0+8)*PSTR + c]   = acc[mt][nl][2] + bv0;
            sm[(r0+8)*PSTR + c+1] = acc[mt][nl][3] + bv1;
        }
    }
    __syncthreads();

    // ---- per-row LN stats: warp w handles rows w*4 .. w*4+3 ----
    for (int r = warp*4; r < warp*4 + 4; r++) {
        const float* row = sm + r*PSTR;
        float s = 0.f, sq = 0.f;
        #pragma unroll
        for (int i = lane; i < Dz; i += 32) {
            float v = row[i];
            s += v; sq += v*v;
        }
        #pragma unroll
        for (int off = 16; off > 0; off >>= 1) {
            s  += __shfl_xor_sync(0xffffffffu, s,  off);
            sq += __shfl_xor_sync(0xffffffffu, sq, off);
        }
        if (lane == 0) {
            float m = s * (1.f/Dz);
            float var = sq * (1.f/Dz) - m*m;
            s_mean[r] = m;
            s_rstd[r] = rsqrtf(var + 1e-5f);
        }
    }
    __syncthreads();

    // ---- normalize + ReLU + store ----
    float* outB = out + ((size_t)b*Tz + t0) * Dz;
    for (int idx = tid; idx < TM*Dz; idx += 256) {
        int r = idx / Dz, c = idx - r*Dz;
        float v = sm[r*PSTR + c];
        float o = (v - s_mean[r]) * s_rstd[r] * __ldg(gamma + c) + __ldg(beta + c);
        outB[(size_t)r*Dz + c] = fmaxf(o, 0.f);
    }
}

// ---------------- pred = h2 @ wl + bl  (warp per row) ----------------
__global__ void pred_kernel(const float* __restrict__ wl,
                            const float* __restrict__ bl,
                            float* __restrict__ pred)
{
    int row  = blockIdx.x * (blockDim.x >> 5) + (threadIdx.x >> 5);
    int lane = threadIdx.x & 31;
    if (row >= ROWS) return;
    const float* hr = g_h2 + (size_t)row * Dz;
    float s = 0.f;
    #pragma unroll
    for (int i = lane; i < Dz; i += 32) s += hr[i] * wl[i];
    #pragma unroll
    for (int off = 16; off > 0; off >>= 1) s += __shfl_xor_sync(0xffffffffu, s, off);
    if (lane == 0) pred[row] = s + bl[0];
}

// ---------------- per-batch inclusive cumsum of durations ----------------
__global__ void scan_kernel(const int* __restrict__ dur) {
    __shared__ int s[Tz];
    int b = blockIdx.x, t = threadIdx.x;
    s[t] = dur[b*Tz + t];
    __syncthreads();
    for (int off = 1; off < Tz; off <<= 1) {
        int v = (t >= off) ? s[t - off] : 0;
        __syncthreads();
        s[t] += v;
        __syncthreads();
    }
    g_cum[b*Tz + t] = s[t];
}

// ---------------- expansion ----------------
__global__ void expand_kernel(const float* __restrict__ x,
                              float* __restrict__ out, int L)
{
    int l = blockIdx.x, b = blockIdx.y;
    const int* cb = g_cum + b*Tz;
    int total = cb[Tz - 1];
    float4* o4 = (float4*)(out + ((size_t)b*L + l) * Dz);
    int tid = threadIdx.x;                 // 96 threads x float4 = 384 floats
    if (l >= total) {
        o4[tid] = make_float4(0.f, 0.f, 0.f, 0.f);
        return;
    }
    int lo = 0, hi = Tz - 1;
    while (lo < hi) {
        int mid = (lo + hi) >> 1;
        if (cb[mid] > l) hi = mid; else lo = mid + 1;
    }
    const float4* x4 = (const float4*)(x + ((size_t)b*Tz + lo) * Dz);
    o4[tid] = x4[tid];
}

// ---------------- launch ----------------
extern "C" void kernel_launch(void* const* d_in, const int* in_sizes, int n_in,
                              void* d_out, int out_size)
{
    const float* x   = (const float*)d_in[0];
    const int*   dur = (const int*)  d_in[1];
    const float* w1  = (const float*)d_in[2];
    const float* b1  = (const float*)d_in[3];
    const float* g1  = (const float*)d_in[4];
    const float* be1 = (const float*)d_in[5];
    const float* w2  = (const float*)d_in[6];
    const float* b2  = (const float*)d_in[7];
    const float* g2  = (const float*)d_in[8];
    const float* be2 = (const float*)d_in[9];
    const float* wl  = (const float*)d_in[10];
    const float* bl  = (const float*)d_in[11];
    float* out = (float*)d_out;

    int L = (out_size - Bz*Tz) / (Bz*Dz);
    float* pred_out = out + (size_t)Bz * L * Dz;

    const int SMEM = (TM + 2) * PSTR * (int)sizeof(float);   // 52768 B
    cudaFuncSetAttribute(conv_ln_relu_mma,
                         cudaFuncAttributeMaxDynamicSharedMemorySize, SMEM);

    const int WN = NKS*NT*32;
    prep_w_kernel<<<(WN + 255)/256, 256>>>(w1, 0);
    prep_w_kernel<<<(WN + 255)/256, 256>>>(w2, 1);

    conv_ln_relu_mma<<<ROWS/TM, 256, SMEM>>>(x, b1, g1, be1, 0);
    conv_ln_relu_mma<<<ROWS/TM, 256, SMEM>>>(x, b2, g2, be2, 1);

    pred_kernel<<<(ROWS + 7)/8, 256>>>(wl, bl, pred_out);

    scan_kernel<<<Bz, Tz>>>(dur);
    expand_kernel<<<dim3(L, Bz), 96>>>(x, out, L);
}

// round 6
// speedup vs baseline: 1.6349x; 1.6349x over previous
#include <cuda_runtime.h>
#include <cuda_bf16.h>

#define Bz   16
#define Tz   512
#define Dz   384
#define Kz   3
#define ROWS (Bz*Tz)       // 8192
#define TM   32            // rows per block
#define NK16 (Kz*24)       // 72 k-steps of 16
#define NT   48            // n-tiles of 8 (384/8)
#define PS   196           // patch stride in uint32 pairs (196%32==4 -> conflict-free frags)
#define SSTR 388           // C-stash stride in floats

// ---------------- scratch (device globals) ----------------
__device__ uint4 g_wb1[NK16*NT*32];   // bf16 weight frags: (bhi0,bhi1,blo0,blo1)
__device__ uint4 g_wb2[NK16*NT*32];
__device__ float g_h1[ROWS*Dz];
__device__ float g_h2[ROWS*Dz];
__device__ int   g_cum[ROWS];

__device__ __forceinline__ unsigned pack_bf16x2(__nv_bfloat16 e0, __nv_bfloat16 e1) {
    return ((unsigned)__bfloat16_as_ushort(e1) << 16) | (unsigned)__bfloat16_as_ushort(e0);
}

__device__ __forceinline__ void mma_bf16(float* d,
    unsigned a0, unsigned a1, unsigned a2, unsigned a3,
    unsigned b0, unsigned b1)
{
    asm volatile(
        "mma.sync.aligned.m16n8k16.row.col.f32.bf16.bf16.f32 "
        "{%0,%1,%2,%3},{%4,%5,%6,%7},{%8,%9},{%0,%1,%2,%3};"
        : "+f"(d[0]), "+f"(d[1]), "+f"(d[2]), "+f"(d[3])
        : "r"(a0), "r"(a1), "r"(a2), "r"(a3), "r"(b0), "r"(b1));
}

// ---------------- weight prep: w[O][I][K] -> bf16 hi/lo fragment layout ----------------
// wb[(ks*NT + nt)*32 + lane]: for lane tig=lane&3, gid=lane>>2; tap=ks/24, kc=ks%24
//   b0 covers k = kc*16 + 2tig, 2tig+1 ; b1 covers k+8 ; n = nt*8+gid
__global__ void prep_w_kernel(const float* __restrict__ w, int stage) {
    uint4* wb = stage ? g_wb2 : g_wb1;
    int idx = blockIdx.x * blockDim.x + threadIdx.x;
    if (idx >= NK16*NT*32) return;
    int lane = idx & 31;
    int nt   = (idx >> 5) % NT;
    int ks   = idx / (NT*32);
    int tig = lane & 3, gid = lane >> 2;
    int tap = ks / 24, kc = ks % 24;
    int n   = nt*8 + gid;
    int k0  = kc*16 + 2*tig;

    float v[4];
    v[0] = w[(size_t)n*Dz*Kz + (size_t)(k0    )*Kz + tap];
    v[1] = w[(size_t)n*Dz*Kz + (size_t)(k0 + 1)*Kz + tap];
    v[2] = w[(size_t)n*Dz*Kz + (size_t)(k0 + 8)*Kz + tap];
    v[3] = w[(size_t)n*Dz*Kz + (size_t)(k0 + 9)*Kz + tap];

    __nv_bfloat16 hi[4], lo[4];
    #pragma unroll
    for (int i = 0; i < 4; i++) {
        hi[i] = __float2bfloat16_rn(v[i]);
        lo[i] = __float2bfloat16_rn(v[i] - __bfloat162float(hi[i]));
    }
    uint4 o;
    o.x = pack_bf16x2(hi[0], hi[1]);   // bhi0
    o.y = pack_bf16x2(hi[2], hi[3]);   // bhi1
    o.z = pack_bf16x2(lo[0], lo[1]);   // blo0
    o.w = pack_bf16x2(lo[2], lo[3]);   // blo1
    wb[idx] = o;
}

// ---------------- fused conv1d(K=3) + LN + ReLU via bf16 3-term mma ----------------
// 8 warps; all cover the same 32 rows, each owns 48 output cols (6 n-tiles).
__global__ void __launch_bounds__(256, 2) conv_ln_relu_mma(
    const float* __restrict__ x_in,
    const float* __restrict__ bias,
    const float* __restrict__ gamma,
    const float* __restrict__ beta,
    int stage)
{
    extern __shared__ unsigned smu[];
    // phase 1: pre-split patch, (TM+2) rows x 192 bf16x2 pairs, stride PS
    unsigned* smA_hi = smu;                       // 34*196
    unsigned* smA_lo = smu + (TM+2)*PS;           // 34*196
    float*    stash  = (float*)smu;               // phase 2: TM x SSTR floats
    __shared__ float s_mean[TM], s_rstd[TM];

    const float* in  = stage ? g_h1  : x_in;
    const uint4* wb  = stage ? g_wb2 : g_wb1;
    float*       out = stage ? g_h2  : g_h1;

    const int tid  = threadIdx.x;
    const int warp = tid >> 5, lane = tid & 31;
    const int tig  = lane & 3, gid = lane >> 2;

    const int tilesPerB = Tz / TM;                 // 16
    const int b  = blockIdx.x / tilesPerB;
    const int t0 = (blockIdx.x % tilesPerB) * TM;
    const float* inB = in + (size_t)b * Tz * Dz;

    // ---- fill pre-split patch rows t0-1 .. t0+TM (34 rows) ----
    for (int i = tid; i < (TM+2)*(Dz/2); i += 256) {
        int pr = i / (Dz/2), pc = i % (Dz/2);
        int t = t0 + pr - 1;
        float2 v = make_float2(0.f, 0.f);
        if (t >= 0 && t < Tz) v = *(const float2*)(inB + (size_t)t*Dz + pc*2);
        __nv_bfloat16 h0 = __float2bfloat16_rn(v.x);
        __nv_bfloat16 h1 = __float2bfloat16_rn(v.y);
        __nv_bfloat16 l0 = __float2bfloat16_rn(v.x - __bfloat162float(h0));
        __nv_bfloat16 l1 = __float2bfloat16_rn(v.y - __bfloat162float(h1));
        smA_hi[pr*PS + pc] = pack_bf16x2(h0, h1);
        smA_lo[pr*PS + pc] = pack_bf16x2(l0, l1);
    }
    __syncthreads();

    // ---- GEMM: warp covers 32 rows x 48 cols ----
    float acc[2][6][4];
    #pragma unroll
    for (int mt = 0; mt < 2; mt++)
        #pragma unroll
        for (int nl = 0; nl < 6; nl++)
            #pragma unroll
            for (int e = 0; e < 4; e++) acc[mt][nl][e] = 0.f;

    #pragma unroll 1
    for (int tap = 0; tap < Kz; tap++) {
        #pragma unroll 1
        for (int kc = 0; kc < 24; kc++) {
            const int ks = tap*24 + kc;
            const int p0 = kc*8 + tig;           // bf16-pair index within row

            // A fragments (hi and lo), conflict-free: (row*PS + p0) distinct mod 32
            unsigned ahi[2][4], alo[2][4];
            #pragma unroll
            for (int mt = 0; mt < 2; mt++) {
                int r0 = (mt*16 + gid + tap) * PS;
                int r1 = r0 + 8*PS;
                ahi[mt][0] = smA_hi[r0 + p0];
                ahi[mt][1] = smA_hi[r1 + p0];
                ahi[mt][2] = smA_hi[r0 + p0 + 4];
                ahi[mt][3] = smA_hi[r1 + p0 + 4];
                alo[mt][0] = smA_lo[r0 + p0];
                alo[mt][1] = smA_lo[r1 + p0];
                alo[mt][2] = smA_lo[r0 + p0 + 4];
                alo[mt][3] = smA_lo[r1 + p0 + 4];
            }

            const uint4* wk = wb + ((size_t)ks*NT + warp*6)*32 + lane;
            #pragma unroll
            for (int nl = 0; nl < 6; nl++) {
                uint4 wv = wk[nl*32];
                #pragma unroll
                for (int mt = 0; mt < 2; mt++) {
                    mma_bf16(acc[mt][nl], ahi[mt][0], ahi[mt][1], ahi[mt][2], ahi[mt][3], wv.x, wv.y);
                    mma_bf16(acc[mt][nl], ahi[mt][0], ahi[mt][1], ahi[mt][2], ahi[mt][3], wv.z, wv.w);
                    mma_bf16(acc[mt][nl], alo[mt][0], alo[mt][1], alo[mt][2], alo[mt][3], wv.x, wv.y);
                }
            }
        }
    }

    // ---- stash C (+bias) into smem (reuse patch region) ----
    __syncthreads();
    #pragma unroll
    for (int mt = 0; mt < 2; mt++) {
        int r0 = mt*16 + gid;
        #pragma unroll
        for (int nl = 0; nl < 6; nl++) {
            int c = warp*48 + nl*8 + tig*2;
            float bv0 = __ldg(bias + c), bv1 = __ldg(bias + c + 1);
            stash[r0*SSTR + c]       = acc[mt][nl][0] + bv0;
            stash[r0*SSTR + c + 1]   = acc[mt][nl][1] + bv1;
            stash[(r0+8)*SSTR + c]   = acc[mt][nl][2] + bv0;
            stash[(r0+8)*SSTR + c+1] = acc[mt][nl][3] + bv1;
        }
    }
    __syncthreads();

    // ---- per-row LN stats: warp w handles rows w*4 .. w*4+3 ----
    for (int r = warp*4; r < warp*4 + 4; r++) {
        const float* row = stash + r*SSTR;
        float s = 0.f, sq = 0.f;
        #pragma unroll
        for (int i = lane; i < Dz; i += 32) {
            float v = row[i];
            s += v; sq += v*v;
        }
        #pragma unroll
        for (int off = 16; off > 0; off >>= 1) {
            s  += __shfl_xor_sync(0xffffffffu, s,  off);
            sq += __shfl_xor_sync(0xffffffffu, sq, off);
        }
        if (lane == 0) {
            float m = s * (1.f/Dz);
            float var = sq * (1.f/Dz) - m*m;
            s_mean[r] = m;
            s_rstd[r] = rsqrtf(var + 1e-5f);
        }
    }
    __syncthreads();

    // ---- normalize + ReLU + store ----
    float* outB = out + ((size_t)b*Tz + t0) * Dz;
    for (int idx = tid; idx < TM*Dz; idx += 256) {
        int r = idx / Dz, c = idx - r*Dz;
        float v = stash[r*SSTR + c];
        float o = (v - s_mean[r]) * s_rstd[r] * __ldg(gamma + c) + __ldg(beta + c);
        outB[(size_t)r*Dz + c] = fmaxf(o, 0.f);
    }
}

// ---------------- pred = h2 @ wl + bl  (warp per row) ----------------
__global__ void pred_kernel(const float* __restrict__ wl,
                            const float* __restrict__ bl,
                            float* __restrict__ pred)
{
    int row  = blockIdx.x * (blockDim.x >> 5) + (threadIdx.x >> 5);
    int lane = threadIdx.x & 31;
    if (row >= ROWS) return;
    const float* hr = g_h2 + (size_t)row * Dz;
    float s = 0.f;
    #pragma unroll
    for (int i = lane; i < Dz; i += 32) s += hr[i] * wl[i];
    #pragma unroll
    for (int off = 16; off > 0; off >>= 1) s += __shfl_xor_sync(0xffffffffu, s, off);
    if (lane == 0) pred[row] = s + bl[0];
}

// ---------------- per-batch inclusive cumsum of durations ----------------
__global__ void scan_kernel(const int* __restrict__ dur) {
    __shared__ int s[Tz];
    int b = blockIdx.x, t = threadIdx.x;
    s[t] = dur[b*Tz + t];
    __syncthreads();
    for (int off = 1; off < Tz; off <<= 1) {
        int v = (t >= off) ? s[t - off] : 0;
        __syncthreads();
        s[t] += v;
        __syncthreads();
    }
    g_cum[b*Tz + t] = s[t];
}

// ---------------- expansion ----------------
__global__ void expand_kernel(const float* __restrict__ x,
                              float* __restrict__ out, int L)
{
    int l = blockIdx.x, b = blockIdx.y;
    const int* cb = g_cum + b*Tz;
    int total = cb[Tz - 1];
    float4* o4 = (float4*)(out + ((size_t)b*L + l) * Dz);
    int tid = threadIdx.x;                 // 96 threads x float4 = 384 floats
    if (l >= total) {
        o4[tid] = make_float4(0.f, 0.f, 0.f, 0.f);
        return;
    }
    int lo = 0, hi = Tz - 1;
    while (lo < hi) {
        int mid = (lo + hi) >> 1;
        if (cb[mid] > l) hi = mid; else lo = mid + 1;
    }
    const float4* x4 = (const float4*)(x + ((size_t)b*Tz + lo) * Dz);
    o4[tid] = x4[tid];
}

// ---------------- launch ----------------
extern "C" void kernel_launch(void* const* d_in, const int* in_sizes, int n_in,
                              void* d_out, int out_size)
{
    const float* x   = (const float*)d_in[0];
    const int*   dur = (const int*)  d_in[1];
    const float* w1  = (const float*)d_in[2];
    const float* b1  = (const float*)d_in[3];
    const float* g1  = (const float*)d_in[4];
    const float* be1 = (const float*)d_in[5];
    const float* w2  = (const float*)d_in[6];
    const float* b2  = (const float*)d_in[7];
    const float* g2  = (const float*)d_in[8];
    const float* be2 = (const float*)d_in[9];
    const float* wl  = (const float*)d_in[10];
    const float* bl  = (const float*)d_in[11];
    float* out = (float*)d_out;

    int L = (out_size - Bz*Tz) / (Bz*Dz);
    float* pred_out = out + (size_t)Bz * L * Dz;

    // smem: max(pre-split patch, C stash)
    int smemPatch = 2 * (TM+2) * PS * (int)sizeof(unsigned);  // 53312
    int smemStash = TM * SSTR * (int)sizeof(float);           // 49664
    int SMEM = smemPatch > smemStash ? smemPatch : smemStash;
    cudaFuncSetAttribute(conv_ln_relu_mma,
                         cudaFuncAttributeMaxDynamicSharedMemorySize, SMEM);

    const int WN = NK16*NT*32;
    prep_w_kernel<<<(WN + 255)/256, 256>>>(w1, 0);
    prep_w_kernel<<<(WN + 255)/256, 256>>>(w2, 1);

    conv_ln_relu_mma<<<ROWS/TM, 256, SMEM>>>(x, b1, g1, be1, 0);
    conv_ln_relu_mma<<<ROWS/TM, 256, SMEM>>>(x, b2, g2, be2, 1);

    pred_kernel<<<(ROWS + 7)/8, 256>>>(wl, bl, pred_out);

    scan_kernel<<<Bz, Tz>>>(dur);
    expand_kernel<<<dim3(L, Bz), 96>>>(x, out, L);
}